// round 8
// baseline (speedup 1.0000x reference)
#include <cuda_runtime.h>
#include <cstdint>

#define BATCH 8
#define SEQ   4096
#define DM    65
#define DH    64
#define NUNITS 640u

// Scratch (__device__ globals; allocation-free rule)
__device__ float g_q [BATCH * SEQ * DH];          // pre-scaled, tf32-rounded
__device__ float g_k [BATCH * SEQ * DH];
__device__ float g_vT[BATCH * DH * SEQ];          // [b][dim][l]
__device__ float g_part [8 * 32 * 4 * 128 * 64];  // partial O per (tile, chunk)
__device__ float g_lpart[8 * 32 * 4 * 128];       // partial row-sums
__device__ unsigned int g_tile_ctr;               // persistent work queue

// ============================ helpers ============================
__device__ __forceinline__ uint32_t smem_u32(const void* p) {
    uint32_t a;
    asm("{ .reg .u64 t; cvta.to.shared.u64 t, %1; cvt.u32.u64 %0, t; }" : "=r"(a) : "l"(p));
    return a;
}
__device__ __forceinline__ float tf32r(float x) {
    uint32_t r; asm("cvt.rna.tf32.f32 %0, %1;" : "=r"(r) : "f"(x));
    return __uint_as_float(r);
}
__device__ __forceinline__ void ldsm4(uint32_t addr, uint32_t r[4]) {
    asm volatile("ldmatrix.sync.aligned.m8n8.x4.shared.b16 {%0,%1,%2,%3}, [%4];"
                 : "=r"(r[0]), "=r"(r[1]), "=r"(r[2]), "=r"(r[3]) : "r"(addr));
}
__device__ __forceinline__ void mma_tf32(float c[4], const uint32_t a[4],
                                         uint32_t b0, uint32_t b1) {
    asm volatile(
        "mma.sync.aligned.m16n8k8.row.col.f32.tf32.tf32.f32 "
        "{%0,%1,%2,%3}, {%4,%5,%6,%7}, {%8,%9}, {%0,%1,%2,%3};"
        : "+f"(c[0]), "+f"(c[1]), "+f"(c[2]), "+f"(c[3])
        : "r"(a[0]), "r"(a[1]), "r"(a[2]), "r"(a[3]), "r"(b0), "r"(b1));
}
// Swizzled byte offset: 256B rows (64 floats), 16B chunks XORed by row&7.
__device__ __forceinline__ uint32_t swz(int row, int colf) {
    return (uint32_t)((row << 8) + ((((colf >> 2) ^ (row & 7))) << 4) + ((colf & 3) << 2));
}

// ============================ merged projections ============================
// One block = 64 rows of x. 8 warps; warp w owns rows 8w..8w+7 (Q/K phases)
// or dims 8w..8w+7 (V^T phase). Thread (r=lane>>2, c4=(lane&3)*4) covers
// cols {c4+16k, k=0..3} -> bank-disjoint 16B W loads (1 wf each, 8-way bcast).
__global__ void __launch_bounds__(256) proj_kernel(
    const float* __restrict__ x,
    const float* __restrict__ Wq, const float* __restrict__ bq,
    const float* __restrict__ Wk, const float* __restrict__ bk,
    const float* __restrict__ Wv, const float* __restrict__ bv)
{
    __shared__ float sW[DM * 64];
    __shared__ float sx[DM][68];     // x transposed: sx[d][row]

    const int tid  = threadIdx.x;
    const int lane = tid & 31;
    const int w    = tid >> 5;
    const int r    = lane >> 2;          // 0..7
    const int c4   = (lane & 3) << 2;    // 0,4,8,12
    const int row0 = blockIdx.x << 6;

    if (blockIdx.x == 0 && tid == 0) g_tile_ctr = 0u;  // reset work queue

    for (int f = tid; f < 64 * DM; f += 256) {
        const int rr = f / DM, d = f - rr * DM;
        sx[d][rr] = x[(size_t)(row0 + rr) * DM + d];
    }

    // ---- phases 0 (Q, scaled) and 1 (K) ----
    #pragma unroll
    for (int ph = 0; ph < 2; ph++) {
        const float* W = (ph == 0) ? Wq : Wk;
        const float* bias = (ph == 0) ? bq : bk;
        float* dst = (ph == 0) ? g_q : g_k;
        const float sc = (ph == 0) ? 0.12403473458920847f : 1.0f;

        __syncthreads();
        for (int f = tid; f < DM * 64; f += 256) sW[f] = W[f];
        __syncthreads();

        float acc[4][4];
        #pragma unroll
        for (int k = 0; k < 4; k++) {
            const float4 bv4 = *(const float4*)&bias[c4 + 16 * k];
            acc[k][0] = bv4.x; acc[k][1] = bv4.y; acc[k][2] = bv4.z; acc[k][3] = bv4.w;
        }
        const int myrow = 8 * w + r;
        #pragma unroll 5
        for (int d = 0; d < DM; d++) {
            const float xv = sx[d][myrow];
            #pragma unroll
            for (int k = 0; k < 4; k++) {
                const float4 w4 = *(const float4*)&sW[d * 64 + c4 + 16 * k];
                acc[k][0] = fmaf(xv, w4.x, acc[k][0]);
                acc[k][1] = fmaf(xv, w4.y, acc[k][1]);
                acc[k][2] = fmaf(xv, w4.z, acc[k][2]);
                acc[k][3] = fmaf(xv, w4.w, acc[k][3]);
            }
        }
        float* p = &dst[(size_t)(row0 + myrow) * 64 + c4];
        #pragma unroll
        for (int k = 0; k < 4; k++)
            *(float4*)&p[16 * k] = make_float4(tf32r(acc[k][0] * sc), tf32r(acc[k][1] * sc),
                                               tf32r(acc[k][2] * sc), tf32r(acc[k][3] * sc));
    }

    // ---- phase 2: V^T (dims as rows, l as cols) ----
    {
        __syncthreads();
        for (int f = tid; f < DM * 64; f += 256) sW[f] = Wv[f];
        __syncthreads();

        const int dim = 8 * w + r;
        const float bias = bv[dim];
        float acc[4][4];
        #pragma unroll
        for (int k = 0; k < 4; k++)
            #pragma unroll
            for (int j = 0; j < 4; j++) acc[k][j] = bias;

        #pragma unroll 5
        for (int d = 0; d < DM; d++) {
            const float wv = sW[d * 64 + dim];
            #pragma unroll
            for (int k = 0; k < 4; k++) {
                const float4 x4 = *(const float4*)&sx[d][c4 + 16 * k];
                acc[k][0] = fmaf(x4.x, wv, acc[k][0]);
                acc[k][1] = fmaf(x4.y, wv, acc[k][1]);
                acc[k][2] = fmaf(x4.z, wv, acc[k][2]);
                acc[k][3] = fmaf(x4.w, wv, acc[k][3]);
            }
        }
        const int bb = row0 >> 12, l0 = row0 & 4095;
        float* p = &g_vT[(size_t)((bb << 6) + dim) * SEQ + l0 + c4];
        #pragma unroll
        for (int k = 0; k < 4; k++)
            *(float4*)&p[16 * k] = make_float4(tf32r(acc[k][0]), tf32r(acc[k][1]),
                                               tf32r(acc[k][2]), tf32r(acc[k][3]));
    }
}

// ============================ flash (split-K, persistent) ============================
// Work unit = (b, qt, chunk): 128 queries x <=16 K-iterations (<=1024 keys).
// No-max softmax => chunk partials (O_num, l) are additive; each unit writes its slot.
__global__ void __launch_bounds__(128, 2) flash_kernel()
{
    __shared__ float sA[128 * 64];   // Q prologue -> K tile (rows 0..63) -> P tile
    __shared__ float sVt[64 * 64];
    const uint32_t sAb = smem_u32(sA);
    const uint32_t sVb = smem_u32(sVt);
    char* sAc = (char*)sA;
    char* sVc = (char*)sVt;

    const int tid  = threadIdx.x;
    const int lane = tid & 31;
    const int w    = tid >> 5;
    const int rowAl  = (lane & 7) | (((lane >> 3) & 1) << 3);
    const int colAsh = (lane >> 4) << 2;
    const int rowBl  = lane & 7;
    const int colB4  = (lane >> 3) << 2;
    const int i0     = lane >> 2;
    const int q2     = (lane & 3) << 1;

    for (;;) {
        if (tid == 0)
            *(volatile unsigned*)sA = atomicAdd(&g_tile_ctr, 1u);
        __syncthreads();
        const unsigned unit = *(volatile unsigned*)sA;
        __syncthreads();
        if (unit >= NUNITS) break;

        // decode: heavy-first (qt descending), chunks of 16 K-iters
        const int r = (int)(unit >> 3);
        const int b = (int)(unit & 7u);
        int qt, ch;
        if (r < 32)      { qt = 31 - (r >> 2); ch = r & 3; }
        else if (r < 56) { const int t = r - 32; const int q3 = t / 3; qt = 23 - q3; ch = t - 3 * q3; }
        else if (r < 72) { const int t = r - 56; qt = 15 - (t >> 1); ch = t & 1; }
        else             { qt = 7 - (r - 72); ch = 0; }
        const int nkt = 2 * qt + 2;
        const int kt0 = ch << 4;
        const int kt1 = (kt0 + 16 < nkt) ? kt0 + 16 : nkt;
        const int q0  = qt << 7;

        // ---- Q prologue: 128x64 into region A (swizzled) ----
        #pragma unroll
        for (int i = 0; i < 16; i++) {
            const int f = tid + i * 128;
            const int row = f >> 4, cc4 = f & 15;
            *(float4*)(sAc + swz(row, cc4 << 2)) =
                *(const float4*)&g_q[(size_t)((b << 12) + q0 + row) * 64 + (cc4 << 2)];
        }
        __syncthreads();

        uint32_t qa[2][8][4];
        #pragma unroll
        for (int rb = 0; rb < 2; rb++)
            #pragma unroll
            for (int kk = 0; kk < 8; kk++)
                ldsm4(sAb + swz(32 * w + 16 * rb + rowAl, 8 * kk + colAsh), qa[rb][kk]);

        float o[2][8][4];
        #pragma unroll
        for (int rb = 0; rb < 2; rb++)
            #pragma unroll
            for (int t = 0; t < 8; t++)
                #pragma unroll
                for (int e = 0; e < 4; e++) o[rb][t][e] = 0.f;
        float rs[4] = {0.f, 0.f, 0.f, 0.f};

        for (int kt = kt0; kt < kt1; kt++) {
            const int k0 = kt << 6;

            __syncthreads();
            #pragma unroll
            for (int i = 0; i < 8; i++) {
                const int f = tid + i * 128;
                const int row = f >> 4, cc4 = f & 15;
                *(float4*)(sAc + swz(row, cc4 << 2)) =
                    *(const float4*)&g_k[(size_t)((b << 12) + k0 + row) * 64 + (cc4 << 2)];
                *(float4*)(sVc + swz(row, cc4 << 2)) =
                    *(const float4*)&g_vT[(size_t)((b << 6) + row) * SEQ + k0 + (cc4 << 2)];
            }
            __syncthreads();

            // ---- MMA1: S = Q K^T ----
            float s[2][8][4];
            #pragma unroll
            for (int t = 0; t < 8; t++) {
                #pragma unroll
                for (int e = 0; e < 4; e++) { s[0][t][e] = 0.f; s[1][t][e] = 0.f; }
                #pragma unroll
                for (int kkp = 0; kkp < 4; kkp++) {
                    uint32_t kb[4];
                    ldsm4(sAb + swz(8 * t + rowBl, 16 * kkp + colB4), kb);
                    mma_tf32(s[0][t], qa[0][2 * kkp],     kb[0], kb[1]);
                    mma_tf32(s[0][t], qa[0][2 * kkp + 1], kb[2], kb[3]);
                    mma_tf32(s[1][t], qa[1][2 * kkp],     kb[0], kb[1]);
                    mma_tf32(s[1][t], qa[1][2 * kkp + 1], kb[2], kb[3]);
                }
            }

            // ---- softmax: exp (no max; scores small), tf32-round, row sums ----
            const bool diag = (kt >= 2 * qt);
            #pragma unroll
            for (int rb = 0; rb < 2; rb++) {
                const int r0 = q0 + 32 * w + 16 * rb + i0;
                const int r1 = r0 + 8;
                float a0 = 0.f, a1 = 0.f;
                #pragma unroll
                for (int t = 0; t < 8; t++) {
                    const int key = k0 + 8 * t + q2;
                    float e0, e1, e2, e3;
                    if (diag) {
                        e0 = (key     <= r0) ? tf32r(__expf(s[rb][t][0])) : 0.f;
                        e1 = (key + 1 <= r0) ? tf32r(__expf(s[rb][t][1])) : 0.f;
                        e2 = (key     <= r1) ? tf32r(__expf(s[rb][t][2])) : 0.f;
                        e3 = (key + 1 <= r1) ? tf32r(__expf(s[rb][t][3])) : 0.f;
                    } else {
                        e0 = tf32r(__expf(s[rb][t][0]));
                        e1 = tf32r(__expf(s[rb][t][1]));
                        e2 = tf32r(__expf(s[rb][t][2]));
                        e3 = tf32r(__expf(s[rb][t][3]));
                    }
                    a0 += e0 + e1; a1 += e2 + e3;
                    s[rb][t][0] = e0; s[rb][t][1] = e1;
                    s[rb][t][2] = e2; s[rb][t][3] = e3;
                }
                rs[2 * rb] += a0; rs[2 * rb + 1] += a1;
            }

            __syncthreads();   // all warps finished reading K from region A

            // ---- stage P (own 32 rows) ----
            #pragma unroll
            for (int rb = 0; rb < 2; rb++) {
                const int pr0 = 32 * w + 16 * rb + i0;
                #pragma unroll
                for (int t = 0; t < 8; t++) {
                    const int col = 8 * t + q2;
                    *(float2*)(sAc + swz(pr0,     col)) = make_float2(s[rb][t][0], s[rb][t][1]);
                    *(float2*)(sAc + swz(pr0 + 8, col)) = make_float2(s[rb][t][2], s[rb][t][3]);
                }
            }
            __syncwarp();

            // ---- MMA2: O += P V ----
            #pragma unroll
            for (int kkp = 0; kkp < 4; kkp++) {
                uint32_t pa[2][2][4];
                #pragma unroll
                for (int rb = 0; rb < 2; rb++) {
                    ldsm4(sAb + swz(32 * w + 16 * rb + rowAl, 16 * kkp +     colAsh), pa[rb][0]);
                    ldsm4(sAb + swz(32 * w + 16 * rb + rowAl, 16 * kkp + 8 + colAsh), pa[rb][1]);
                }
                #pragma unroll
                for (int t = 0; t < 8; t++) {
                    uint32_t vb[4];
                    ldsm4(sVb + swz(8 * t + rowBl, 16 * kkp + colB4), vb);
                    mma_tf32(o[0][t], pa[0][0], vb[0], vb[1]);
                    mma_tf32(o[0][t], pa[0][1], vb[2], vb[3]);
                    mma_tf32(o[1][t], pa[1][0], vb[0], vb[1]);
                    mma_tf32(o[1][t], pa[1][1], vb[2], vb[3]);
                }
            }
        }

        // ---- epilogue: reduce row sums, write UN-normalized partials to slot ----
        #pragma unroll
        for (int j = 0; j < 4; j++) {
            rs[j] += __shfl_xor_sync(0xffffffffu, rs[j], 1);
            rs[j] += __shfl_xor_sync(0xffffffffu, rs[j], 2);
        }
        const int slot = (((b << 5) + qt) << 2) + ch;
        float* po = &g_part[(size_t)slot << 13];
        #pragma unroll
        for (int rb = 0; rb < 2; rb++) {
            const int r0l = 32 * w + 16 * rb + i0;
            float* o0 = &po[r0l * 64];
            float* o1 = o0 + 8 * 64;
            #pragma unroll
            for (int t = 0; t < 8; t++) {
                *(float2*)&o0[8 * t + q2] = make_float2(o[rb][t][0], o[rb][t][1]);
                *(float2*)&o1[8 * t + q2] = make_float2(o[rb][t][2], o[rb][t][3]);
            }
            if ((lane & 3) == 0) {
                g_lpart[slot * 128 + r0l]     = rs[2 * rb];
                g_lpart[slot * 128 + r0l + 8] = rs[2 * rb + 1];
            }
        }
        __syncthreads();   // region A reads done before next unit's queue write
    }
}

// ============================ normalize / combine ============================
// One block per q-tile (b, qt): out = (sum_c O_c) / (sum_c l_c), fixed order => deterministic.
__global__ void __launch_bounds__(256) norm_kernel(float* __restrict__ out)
{
    const int tile = blockIdx.x;          // (b<<5)+qt
    const int b = tile >> 5, qt = tile & 31;
    const int nc = (qt + 8) >> 3;         // chunks for this tile
    const int tid = threadIdx.x;
    const int row = tid >> 1;
    const int c0  = (tid & 1) << 5;       // 32 cols per thread
    const size_t base = (size_t)tile << 15;   // tile*4*8192

    float acc[32];
    #pragma unroll
    for (int i = 0; i < 32; i++) acc[i] = 0.f;
    float l = 0.f;

    for (int c = 0; c < nc; c++) {
        const float* p = &g_part[base + ((size_t)c << 13) + row * 64 + c0];
        #pragma unroll
        for (int i = 0; i < 8; i++) {
            const float4 v = *(const float4*)&p[i * 4];
            acc[4 * i]     += v.x;
            acc[4 * i + 1] += v.y;
            acc[4 * i + 2] += v.z;
            acc[4 * i + 3] += v.w;
        }
        l += g_lpart[(tile * 4 + c) * 128 + row];
    }
    const float inv = 1.f / l;
    float* po = &out[(size_t)((b << 12) + (qt << 7) + row) * 64 + c0];
    #pragma unroll
    for (int i = 0; i < 8; i++)
        *(float4*)&po[i * 4] = make_float4(acc[4*i] * inv, acc[4*i+1] * inv,
                                           acc[4*i+2] * inv, acc[4*i+3] * inv);
}

// ============================ launch ============================
extern "C" void kernel_launch(void* const* d_in, const int* in_sizes, int n_in,
                              void* d_out, int out_size)
{
    const float* x  = (const float*)d_in[0];
    const float* Wq = (const float*)d_in[1];
    const float* bq = (const float*)d_in[2];
    const float* Wk = (const float*)d_in[3];
    const float* bk = (const float*)d_in[4];
    const float* Wv = (const float*)d_in[5];
    const float* bv = (const float*)d_in[6];
    float* out = (float*)d_out;

    proj_kernel<<<(BATCH * SEQ) / 64, 256>>>(x, Wq, bq, Wk, bk, Wv, bv);
    flash_kernel<<<296, 128>>>();          // persistent, 640 work units
    norm_kernel<<<256, 256>>>(out);
}

// round 9
// speedup vs baseline: 1.8942x; 1.8942x over previous
#include <cuda_runtime.h>
#include <cuda_fp16.h>
#include <cstdint>

#define BATCH 8
#define SEQ   4096
#define DM    65
#define DH    64
#define NUNITS 640u

// Scratch (__device__ globals; allocation-free rule)
__device__ __half g_q [BATCH * SEQ * DH];         // pre-scaled 1/sqrt(65)
__device__ __half g_k [BATCH * SEQ * DH];
__device__ __half g_vT[BATCH * DH * SEQ];         // [b][dim][l]
__device__ float  g_part [8 * 32 * 4 * 128 * 64]; // partial O per (tile, chunk)
__device__ float  g_lpart[8 * 32 * 4 * 128];      // partial row-sums
__device__ unsigned int g_tile_ctr;               // persistent work queue

// ============================ helpers ============================
__device__ __forceinline__ uint32_t smem_u32(const void* p) {
    uint32_t a;
    asm("{ .reg .u64 t; cvta.to.shared.u64 t, %1; cvt.u32.u64 %0, t; }" : "=r"(a) : "l"(p));
    return a;
}
__device__ __forceinline__ void ldsm4(uint32_t addr, uint32_t r[4]) {
    asm volatile("ldmatrix.sync.aligned.m8n8.x4.shared.b16 {%0,%1,%2,%3}, [%4];"
                 : "=r"(r[0]), "=r"(r[1]), "=r"(r[2]), "=r"(r[3]) : "r"(addr));
}
// D(16x8,f32) += A(16x16,f16) * B(16x8,f16)
__device__ __forceinline__ void mma_f16(float c[4], const uint32_t a[4],
                                        uint32_t b0, uint32_t b1) {
    asm volatile(
        "mma.sync.aligned.m16n8k16.row.col.f32.f16.f16.f32 "
        "{%0,%1,%2,%3}, {%4,%5,%6,%7}, {%8,%9}, {%0,%1,%2,%3};"
        : "+f"(c[0]), "+f"(c[1]), "+f"(c[2]), "+f"(c[3])
        : "r"(a[0]), "r"(a[1]), "r"(a[2]), "r"(a[3]), "r"(b0), "r"(b1));
}
__device__ __forceinline__ uint32_t pkh2(float a, float b) {
    __half2 h = __floats2half2_rn(a, b);
    return *reinterpret_cast<uint32_t*>(&h);
}
__device__ __forceinline__ void cpa16(uint32_t s, const void* g) {
    asm volatile("cp.async.cg.shared.global [%0], [%1], 16;" :: "r"(s), "l"(g) : "memory");
}
#define CP_COMMIT() asm volatile("cp.async.commit_group;" ::: "memory")
#define CP_WAIT0()  asm volatile("cp.async.wait_group 0;" ::: "memory")
#define CP_WAIT1()  asm volatile("cp.async.wait_group 1;" ::: "memory")
#define CP_WAIT2()  asm volatile("cp.async.wait_group 2;" ::: "memory")
// fp16 tile row = 64 halfs = 128B = 8 chunks of 16B; chunk XOR-swizzled by row&7
__device__ __forceinline__ uint32_t swzh(int row, int ch) {
    return (uint32_t)((row << 7) + (((ch ^ (row & 7))) << 4));
}

// ============================ merged projections ============================
// 128 threads, 64 rows of x per block. Q/K: thread = 4 rows x 8 cols.
// V^T: thread = 4 dims x 8 l. fp16 outputs.
__global__ void __launch_bounds__(128) proj_kernel(
    const float* __restrict__ x,
    const float* __restrict__ Wq, const float* __restrict__ bq,
    const float* __restrict__ Wk, const float* __restrict__ bk,
    const float* __restrict__ Wv, const float* __restrict__ bv)
{
    __shared__ float sW[DM * 64];
    __shared__ float sx[DM][68];     // x transposed: sx[d][row]

    const int tid  = threadIdx.x;
    const int row0 = blockIdx.x << 6;
    const int rg4  = (tid >> 3) << 2;   // 0,4,...,60
    const int cg8  = (tid & 7) << 3;    // 0,8,...,56

    if (blockIdx.x == 0 && tid == 0) g_tile_ctr = 0u;

    for (int f = tid; f < 64 * DM; f += 128) {
        const int rr = f / DM, d = f - rr * DM;
        sx[d][rr] = x[(size_t)(row0 + rr) * DM + d];
    }

    // ---- phases 0 (Q, scaled) and 1 (K) ----
    #pragma unroll
    for (int ph = 0; ph < 2; ph++) {
        const float* W = (ph == 0) ? Wq : Wk;
        const float* bias = (ph == 0) ? bq : bk;
        __half* dst = (ph == 0) ? g_q : g_k;
        const float sc = (ph == 0) ? 0.12403473458920847f : 1.0f;

        __syncthreads();
        for (int f = tid; f < DM * 64; f += 128) sW[f] = W[f];
        __syncthreads();

        float acc[4][8];
        #pragma unroll
        for (int i = 0; i < 4; i++)
            #pragma unroll
            for (int j = 0; j < 8; j++) acc[i][j] = bias[cg8 + j];

        #pragma unroll 5
        for (int d = 0; d < DM; d++) {
            const float4 x4 = *(const float4*)&sx[d][rg4];
            const float4 wA = *(const float4*)&sW[d * 64 + cg8];
            const float4 wB = *(const float4*)&sW[d * 64 + cg8 + 4];
            const float xv[4] = {x4.x, x4.y, x4.z, x4.w};
            const float wv[8] = {wA.x, wA.y, wA.z, wA.w, wB.x, wB.y, wB.z, wB.w};
            #pragma unroll
            for (int i = 0; i < 4; i++)
                #pragma unroll
                for (int j = 0; j < 8; j++)
                    acc[i][j] = fmaf(xv[i], wv[j], acc[i][j]);
        }
        #pragma unroll
        for (int i = 0; i < 4; i++) {
            uint4 u;
            u.x = pkh2(acc[i][0] * sc, acc[i][1] * sc);
            u.y = pkh2(acc[i][2] * sc, acc[i][3] * sc);
            u.z = pkh2(acc[i][4] * sc, acc[i][5] * sc);
            u.w = pkh2(acc[i][6] * sc, acc[i][7] * sc);
            *(uint4*)&dst[(size_t)(row0 + rg4 + i) * 64 + cg8] = u;
        }
    }

    // ---- phase 2: V^T (4 dims x 8 l per thread) ----
    {
        __syncthreads();
        for (int f = tid; f < DM * 64; f += 128) sW[f] = Wv[f];
        __syncthreads();

        float acc[4][8];
        #pragma unroll
        for (int i = 0; i < 4; i++)
            #pragma unroll
            for (int j = 0; j < 8; j++) acc[i][j] = bv[rg4 + i];

        #pragma unroll 5
        for (int d = 0; d < DM; d++) {
            const float4 w4 = *(const float4*)&sW[d * 64 + rg4];
            const float4 xA = *(const float4*)&sx[d][cg8];
            const float4 xB = *(const float4*)&sx[d][cg8 + 4];
            const float wv[4] = {w4.x, w4.y, w4.z, w4.w};
            const float xv[8] = {xA.x, xA.y, xA.z, xA.w, xB.x, xB.y, xB.z, xB.w};
            #pragma unroll
            for (int i = 0; i < 4; i++)
                #pragma unroll
                for (int j = 0; j < 8; j++)
                    acc[i][j] = fmaf(xv[j], wv[i], acc[i][j]);
        }
        const int bb = row0 >> 12, l0 = row0 & 4095;
        #pragma unroll
        for (int i = 0; i < 4; i++) {
            uint4 u;
            u.x = pkh2(acc[i][0], acc[i][1]);
            u.y = pkh2(acc[i][2], acc[i][3]);
            u.z = pkh2(acc[i][4], acc[i][5]);
            u.w = pkh2(acc[i][6], acc[i][7]);
            *(uint4*)&g_vT[(size_t)((bb << 6) + rg4 + i) * SEQ + l0 + cg8] = u;
        }
    }
}

// ============================ flash (fp16 mma, split-K, cp.async 2-stage) ============================
__global__ void __launch_bounds__(128, 2) flash_kernel()
{
    __shared__ __align__(16) __half sK[2][64 * 64];
    __shared__ __align__(16) __half sV[2][64 * 64];
    __shared__ __align__(16) __half sP[128 * 64];   // Q staging, then P; [0] aliased as queue slot

    const uint32_t sKb[2] = { smem_u32(sK[0]), smem_u32(sK[1]) };
    const uint32_t sVb[2] = { smem_u32(sV[0]), smem_u32(sV[1]) };
    const uint32_t sPb = smem_u32(sP);
    char* sPc = (char*)sP;

    const int tid  = threadIdx.x;
    const int lane = tid & 31;
    const int w    = tid >> 5;
    // ldmatrix lane addressing
    const int rowA = lane & 15;                              // A: 16 rows
    const int chA  = lane >> 4;                              // A: +chunk
    const int rowB = (lane & 7) + ((lane >> 4) << 3);        // B: 8 rows, +8 for hi half
    const int chB  = (lane >> 3) & 1;                        // B: +chunk
    const int i0   = lane >> 2;
    const int q2   = (lane & 3) << 1;

    for (;;) {
        if (tid == 0)
            *(volatile unsigned*)sP = atomicAdd(&g_tile_ctr, 1u);
        __syncthreads();
        const unsigned unit = *(volatile unsigned*)sP;
        __syncthreads();
        if (unit >= NUNITS) break;

        // decode: heavy-first (qt descending), chunks of 16 K-iterations
        const int r = (int)(unit >> 3);
        const int b = (int)(unit & 7u);
        int qt, ch;
        if (r < 32)      { qt = 31 - (r >> 2); ch = r & 3; }
        else if (r < 56) { const int t = r - 32; const int q3 = t / 3; qt = 23 - q3; ch = t - 3 * q3; }
        else if (r < 72) { const int t = r - 56; qt = 15 - (t >> 1); ch = t & 1; }
        else             { qt = 7 - (r - 72); ch = 0; }
        const int nkt = 2 * qt + 2;
        const int kt0 = ch << 4;
        const int kt1 = (kt0 + 16 < nkt) ? kt0 + 16 : nkt;
        const int q0  = qt << 7;

        // ---- async fills: Q (into sP), then K/V stage 0 and 1 ----
        #pragma unroll
        for (int i = 0; i < 8; i++) {
            const int f = tid + i * 128;
            const int row = f >> 3, cc = f & 7;
            cpa16(sPb + swzh(row, cc), &g_q[(size_t)((b << 12) + q0 + row) * 64 + cc * 8]);
        }
        CP_COMMIT();
        {
            const int k0 = kt0 << 6;
            #pragma unroll
            for (int i = 0; i < 4; i++) {
                const int f = tid + i * 128;
                const int row = f >> 3, cc = f & 7;
                cpa16(sKb[0] + swzh(row, cc), &g_k[(size_t)((b << 12) + k0 + row) * 64 + cc * 8]);
                cpa16(sVb[0] + swzh(row, cc), &g_vT[(size_t)((b << 6) + row) * SEQ + k0 + cc * 8]);
            }
            CP_COMMIT();
        }
        const bool has2 = (kt0 + 1 < kt1);
        if (has2) {
            const int k0 = (kt0 + 1) << 6;
            #pragma unroll
            for (int i = 0; i < 4; i++) {
                const int f = tid + i * 128;
                const int row = f >> 3, cc = f & 7;
                cpa16(sKb[1] + swzh(row, cc), &g_k[(size_t)((b << 12) + k0 + row) * 64 + cc * 8]);
                cpa16(sVb[1] + swzh(row, cc), &g_vT[(size_t)((b << 6) + row) * SEQ + k0 + cc * 8]);
            }
            CP_COMMIT();
            CP_WAIT2();   // Q group retired
        } else {
            CP_WAIT1();
        }
        __syncthreads();

        // ---- Q fragments (A): 2 row-blocks x 4 k-steps ----
        uint32_t qa[2][4][4];
        #pragma unroll
        for (int rb = 0; rb < 2; rb++)
            #pragma unroll
            for (int ks = 0; ks < 4; ks++)
                ldsm4(sPb + swzh(32 * w + 16 * rb + rowA, 2 * ks + chA), qa[rb][ks]);
        __syncwarp();

        float o[2][8][4];
        #pragma unroll
        for (int rb = 0; rb < 2; rb++)
            #pragma unroll
            for (int t = 0; t < 8; t++)
                #pragma unroll
                for (int e = 0; e < 4; e++) o[rb][t][e] = 0.f;
        float rs[4] = {0.f, 0.f, 0.f, 0.f};

        for (int kt = kt0; kt < kt1; kt++) {
            const int cur = (kt - kt0) & 1;
            const int k0  = kt << 6;

            if (kt + 1 < kt1) { CP_WAIT1(); } else { CP_WAIT0(); }
            __syncthreads();   // buf[cur] filled & visible; prior-iter qa/P reads done

            // ---- MMA1: S = Q K^T ----
            float s[2][8][4];
            #pragma unroll
            for (int t = 0; t < 8; t++)
                #pragma unroll
                for (int e = 0; e < 4; e++) { s[0][t][e] = 0.f; s[1][t][e] = 0.f; }
            #pragma unroll
            for (int ks = 0; ks < 4; ks++)
                #pragma unroll
                for (int tp = 0; tp < 4; tp++) {
                    uint32_t kb[4];
                    ldsm4(sKb[cur] + swzh(16 * tp + rowB, 2 * ks + chB), kb);
                    mma_f16(s[0][2 * tp],     qa[0][ks], kb[0], kb[1]);
                    mma_f16(s[0][2 * tp + 1], qa[0][ks], kb[2], kb[3]);
                    mma_f16(s[1][2 * tp],     qa[1][ks], kb[0], kb[1]);
                    mma_f16(s[1][2 * tp + 1], qa[1][ks], kb[2], kb[3]);
                }

            // ---- softmax: exp (no max; scores small), row sums, P -> fp16 ----
            const bool diag = (kt >= 2 * qt);
            #pragma unroll
            for (int rb = 0; rb < 2; rb++) {
                const int r0 = q0 + 32 * w + 16 * rb + i0;
                const int r1 = r0 + 8;
                const int pr0 = 32 * w + 16 * rb + i0;
                float a0 = 0.f, a1 = 0.f;
                #pragma unroll
                for (int t = 0; t < 8; t++) {
                    const int key = k0 + 8 * t + q2;
                    float e0, e1, e2, e3;
                    if (diag) {
                        e0 = (key     <= r0) ? __expf(s[rb][t][0]) : 0.f;
                        e1 = (key + 1 <= r0) ? __expf(s[rb][t][1]) : 0.f;
                        e2 = (key     <= r1) ? __expf(s[rb][t][2]) : 0.f;
                        e3 = (key + 1 <= r1) ? __expf(s[rb][t][3]) : 0.f;
                    } else {
                        e0 = __expf(s[rb][t][0]);
                        e1 = __expf(s[rb][t][1]);
                        e2 = __expf(s[rb][t][2]);
                        e3 = __expf(s[rb][t][3]);
                    }
                    const uint32_t p01 = pkh2(e0, e1);
                    const uint32_t p23 = pkh2(e2, e3);
                    // sum what MMA2 will actually multiply (fp16-rounded)
                    const __half2 h01 = *reinterpret_cast<const __half2*>(&p01);
                    const __half2 h23 = *reinterpret_cast<const __half2*>(&p23);
                    a0 += __half2float(__low2half(h01)) + __half2float(__high2half(h01));
                    a1 += __half2float(__low2half(h23)) + __half2float(__high2half(h23));
                    *(uint32_t*)(sPc + swzh(pr0,     t) + (q2 << 1)) = p01;
                    *(uint32_t*)(sPc + swzh(pr0 + 8, t) + (q2 << 1)) = p23;
                }
                rs[2 * rb] += a0; rs[2 * rb + 1] += a1;
            }
            __syncwarp();

            // ---- MMA2: O += P V ----
            #pragma unroll
            for (int ks = 0; ks < 4; ks++) {
                uint32_t pa[2][4];
                ldsm4(sPb + swzh(32 * w +      rowA, 2 * ks + chA), pa[0]);
                ldsm4(sPb + swzh(32 * w + 16 + rowA, 2 * ks + chA), pa[1]);
                #pragma unroll
                for (int tp = 0; tp < 4; tp++) {
                    uint32_t vb[4];
                    ldsm4(sVb[cur] + swzh(16 * tp + rowB, 2 * ks + chB), vb);
                    mma_f16(o[0][2 * tp],     pa[0], vb[0], vb[1]);
                    mma_f16(o[0][2 * tp + 1], pa[0], vb[2], vb[3]);
                    mma_f16(o[1][2 * tp],     pa[1], vb[0], vb[1]);
                    mma_f16(o[1][2 * tp + 1], pa[1], vb[2], vb[3]);
                }
            }

            __syncthreads();   // all reads of buf[cur] complete
            if (kt + 2 < kt1) {
                const int kn = (kt + 2) << 6;
                #pragma unroll
                for (int i = 0; i < 4; i++) {
                    const int f = tid + i * 128;
                    const int row = f >> 3, cc = f & 7;
                    cpa16(sKb[cur] + swzh(row, cc), &g_k[(size_t)((b << 12) + kn + row) * 64 + cc * 8]);
                    cpa16(sVb[cur] + swzh(row, cc), &g_vT[(size_t)((b << 6) + row) * SEQ + kn + cc * 8]);
                }
                CP_COMMIT();
            }
        }

        // ---- epilogue: reduce row sums, write un-normalized partials ----
        #pragma unroll
        for (int j = 0; j < 4; j++) {
            rs[j] += __shfl_xor_sync(0xffffffffu, rs[j], 1);
            rs[j] += __shfl_xor_sync(0xffffffffu, rs[j], 2);
        }
        const int slot = (((b << 5) + qt) << 2) + ch;
        float* po = &g_part[(size_t)slot << 13];
        #pragma unroll
        for (int rb = 0; rb < 2; rb++) {
            const int r0l = 32 * w + 16 * rb + i0;
            float* o0 = &po[r0l * 64];
            float* o1 = o0 + 8 * 64;
            #pragma unroll
            for (int t = 0; t < 8; t++) {
                *(float2*)&o0[8 * t + q2] = make_float2(o[rb][t][0], o[rb][t][1]);
                *(float2*)&o1[8 * t + q2] = make_float2(o[rb][t][2], o[rb][t][3]);
            }
            if ((lane & 3) == 0) {
                g_lpart[slot * 128 + r0l]     = rs[2 * rb];
                g_lpart[slot * 128 + r0l + 8] = rs[2 * rb + 1];
            }
        }
    }
}

// ============================ normalize / combine ============================
__global__ void __launch_bounds__(256) norm_kernel(float* __restrict__ out)
{
    const int tile = blockIdx.x;          // (b<<5)+qt
    const int b = tile >> 5, qt = tile & 31;
    const int nc = (qt + 8) >> 3;
    const int tid = threadIdx.x;
    const int row = tid >> 1;
    const int c0  = (tid & 1) << 5;
    const size_t base = (size_t)tile << 15;

    float acc[32];
    #pragma unroll
    for (int i = 0; i < 32; i++) acc[i] = 0.f;
    float l = 0.f;

    for (int c = 0; c < nc; c++) {
        const float* p = &g_part[base + ((size_t)c << 13) + row * 64 + c0];
        #pragma unroll
        for (int i = 0; i < 8; i++) {
            const float4 v = *(const float4*)&p[i * 4];
            acc[4 * i]     += v.x;
            acc[4 * i + 1] += v.y;
            acc[4 * i + 2] += v.z;
            acc[4 * i + 3] += v.w;
        }
        l += g_lpart[(tile * 4 + c) * 128 + row];
    }
    const float inv = 1.f / l;
    float* po = &out[(size_t)((b << 12) + (qt << 7) + row) * 64 + c0];
    #pragma unroll
    for (int i = 0; i < 8; i++)
        *(float4*)&po[i * 4] = make_float4(acc[4*i] * inv, acc[4*i+1] * inv,
                                           acc[4*i+2] * inv, acc[4*i+3] * inv);
}

// ============================ launch ============================
extern "C" void kernel_launch(void* const* d_in, const int* in_sizes, int n_in,
                              void* d_out, int out_size)
{
    const float* x  = (const float*)d_in[0];
    const float* Wq = (const float*)d_in[1];
    const float* bq = (const float*)d_in[2];
    const float* Wk = (const float*)d_in[3];
    const float* bk = (const float*)d_in[4];
    const float* Wv = (const float*)d_in[5];
    const float* bv = (const float*)d_in[6];
    float* out = (float*)d_out;

    proj_kernel<<<(BATCH * SEQ) / 64, 128>>>(x, Wq, bq, Wk, bk, Wv, bv);
    flash_kernel<<<296, 128>>>();          // persistent, 640 split-K units
    norm_kernel<<<256, 256>>>(out);
}

// round 10
// speedup vs baseline: 2.4446x; 1.2906x over previous
#include <cuda_runtime.h>
#include <cuda_fp16.h>
#include <cstdint>

#define BATCH 8
#define SEQ   4096
#define DM    65
#define DH    64
#define NUNITS 640u

// Scratch (__device__ globals; allocation-free rule)
__device__ __half g_q [BATCH * SEQ * DH];         // pre-scaled 1/sqrt(65)
__device__ __half g_k [BATCH * SEQ * DH];
__device__ __half g_vT[BATCH * DH * SEQ];         // [b][dim][l]
__device__ float  g_part [8 * 32 * 4 * 128 * 64]; // partial O per (tile, chunk)
__device__ float  g_lpart[8 * 32 * 4 * 128];      // partial row-sums
__device__ unsigned int g_tile_ctr;               // persistent work queue

// ============================ helpers ============================
__device__ __forceinline__ uint32_t smem_u32(const void* p) {
    uint32_t a;
    asm("{ .reg .u64 t; cvta.to.shared.u64 t, %1; cvt.u32.u64 %0, t; }" : "=r"(a) : "l"(p));
    return a;
}
__device__ __forceinline__ void ldsm4(uint32_t addr, uint32_t r[4]) {
    asm volatile("ldmatrix.sync.aligned.m8n8.x4.shared.b16 {%0,%1,%2,%3}, [%4];"
                 : "=r"(r[0]), "=r"(r[1]), "=r"(r[2]), "=r"(r[3]) : "r"(addr));
}
__device__ __forceinline__ void ldsm4t(uint32_t addr, uint32_t r[4]) {
    asm volatile("ldmatrix.sync.aligned.m8n8.x4.trans.shared.b16 {%0,%1,%2,%3}, [%4];"
                 : "=r"(r[0]), "=r"(r[1]), "=r"(r[2]), "=r"(r[3]) : "r"(addr));
}
// D(16x8,f32) += A(16x16,f16) * B(16x8,f16)
__device__ __forceinline__ void mma_f16(float c[4], const uint32_t a[4],
                                        uint32_t b0, uint32_t b1) {
    asm volatile(
        "mma.sync.aligned.m16n8k16.row.col.f32.f16.f16.f32 "
        "{%0,%1,%2,%3}, {%4,%5,%6,%7}, {%8,%9}, {%0,%1,%2,%3};"
        : "+f"(c[0]), "+f"(c[1]), "+f"(c[2]), "+f"(c[3])
        : "r"(a[0]), "r"(a[1]), "r"(a[2]), "r"(a[3]), "r"(b0), "r"(b1));
}
__device__ __forceinline__ uint32_t pkh2(float a, float b) {
    __half2 h = __floats2half2_rn(a, b);
    return *reinterpret_cast<uint32_t*>(&h);
}
__device__ __forceinline__ void cpa16(uint32_t s, const void* g) {
    asm volatile("cp.async.cg.shared.global [%0], [%1], 16;" :: "r"(s), "l"(g) : "memory");
}
#define CP_COMMIT() asm volatile("cp.async.commit_group;" ::: "memory")
#define CP_WAIT0()  asm volatile("cp.async.wait_group 0;" ::: "memory")
#define CP_WAIT1()  asm volatile("cp.async.wait_group 1;" ::: "memory")
#define CP_WAIT2()  asm volatile("cp.async.wait_group 2;" ::: "memory")
// fp16 tile row = 64 halfs = 128B = 8 chunks of 16B; chunk XOR-swizzled by row&7
__device__ __forceinline__ uint32_t swzh(int row, int ch) {
    return (uint32_t)((row << 7) + (((ch ^ (row & 7))) << 4));
}

// ============================ tensor-core projections ============================
// Block = 128 rows of x, 128 threads (4 warps). K=65 split: 64 dims via fp16 MMA,
// remainder (x[:,64] outer W[64,:]) + bias added fp32 in epilogue.
// Q/K: D[l][col] = A(x tile) x B(W^T via ldsm.trans). V^T: D[dim][l] = A(Wv^T via
// ldsm.trans, B-style addr) x B(x tile) -> already-transposed coalesced stores.
__global__ void __launch_bounds__(128) proj_kernel(
    const float* __restrict__ x,
    const float* __restrict__ Wq, const float* __restrict__ bq,
    const float* __restrict__ Wk, const float* __restrict__ bk,
    const float* __restrict__ Wv, const float* __restrict__ bv)
{
    __shared__ __align__(16) __half sX[128 * 64];
    __shared__ __align__(16) __half sWh[64 * 64];
    __shared__ float sx64[128];
    __shared__ float sw64[64];
    __shared__ float sbias[64];

    const int tid  = threadIdx.x;
    const int lane = tid & 31;
    const int w    = tid >> 5;
    const int row0 = blockIdx.x << 7;
    const uint32_t sXb = smem_u32(sX);
    const uint32_t sWb = smem_u32(sWh);
    char* sXc = (char*)sX;
    char* sWc = (char*)sWh;

    if (blockIdx.x == 0 && tid == 0) g_tile_ctr = 0u;

    // ---- x tile: 128 rows x 64 dims -> fp16 swizzled (scalar loads: 65-stride) ----
    #pragma unroll
    for (int i = 0; i < 32; i++) {
        const int f = tid + i * 128;
        const int row = f >> 5, d2 = f & 31;   // d = 2*d2
        const size_t gb = (size_t)(row0 + row) * DM + 2 * d2;
        *(uint32_t*)(sXc + swzh(row, d2 >> 2) + ((d2 & 3) << 2)) = pkh2(x[gb], x[gb + 1]);
    }
    sx64[tid] = x[(size_t)(row0 + tid) * DM + 64];

    // ldmatrix lane patterns
    const int rA = lane & 15, cA = lane >> 4;                          // A-load / trans-B
    const int rB = (lane & 7) + ((lane >> 4) << 3), cB = (lane >> 3) & 1;  // B-load / trans-A
    const int i0 = lane >> 2, q2 = (lane & 3) << 1;

    // ---- phases 0 (Q, scaled) and 1 (K): out[l][col] ----
    #pragma unroll
    for (int ph = 0; ph < 2; ph++) {
        const float* W = (ph == 0) ? Wq : Wk;
        const float* bias = (ph == 0) ? bq : bk;
        __half* dst = (ph == 0) ? g_q : g_k;
        const float sc = (ph == 0) ? 0.12403473458920847f : 1.0f;

        __syncthreads();   // previous phase readers of sWh done
        #pragma unroll
        for (int i = 0; i < 8; i++) {      // W[:64,:] fp32 -> fp16 swizzled row-major
            const int f = tid + i * 128;   // 1024 float4
            const int d = f >> 4, c4 = (f & 15) << 2;
            const float4 v = *(const float4*)&W[d * 64 + c4];
            char* p = sWc + swzh(d, c4 >> 3) + ((c4 & 7) << 1);
            *(uint32_t*)p       = pkh2(v.x, v.y);
            *(uint32_t*)(p + 4) = pkh2(v.z, v.w);
        }
        if (tid < 64) { sw64[tid] = W[64 * 64 + tid]; sbias[tid] = bias[tid]; }
        __syncthreads();

        // A fragments: warp's 32 l-rows, 4 k-steps
        uint32_t qa[2][4][4];
        #pragma unroll
        for (int rb = 0; rb < 2; rb++)
            #pragma unroll
            for (int ks = 0; ks < 4; ks++)
                ldsm4(sXb + swzh(32 * w + 16 * rb + rA, 2 * ks + cA), qa[rb][ks]);

        float acc[2][8][4];
        #pragma unroll
        for (int rb = 0; rb < 2; rb++)
            #pragma unroll
            for (int t = 0; t < 8; t++)
                #pragma unroll
                for (int e = 0; e < 4; e++) acc[rb][t][e] = 0.f;

        #pragma unroll
        for (int ks = 0; ks < 4; ks++)
            #pragma unroll
            for (int tp = 0; tp < 4; tp++) {
                uint32_t bt[4];
                ldsm4t(sWb + swzh(16 * ks + rA, 2 * tp + cA), bt);
                #pragma unroll
                for (int rb = 0; rb < 2; rb++) {
                    mma_f16(acc[rb][2 * tp],     qa[rb][ks], bt[0], bt[1]);
                    mma_f16(acc[rb][2 * tp + 1], qa[rb][ks], bt[2], bt[3]);
                }
            }

        // epilogue: remainder + bias (fp32), scale, fp16 store
        #pragma unroll
        for (int rb = 0; rb < 2; rb++) {
            const int r0l = 32 * w + 16 * rb + i0;
            const int r1l = r0l + 8;
            const float x0 = sx64[r0l], x1 = sx64[r1l];
            #pragma unroll
            for (int t = 0; t < 8; t++) {
                const int col = 8 * t + q2;
                const float b0 = sbias[col], b1 = sbias[col + 1];
                const float w0 = sw64[col], w1 = sw64[col + 1];
                const float e0 = (acc[rb][t][0] + b0 + x0 * w0) * sc;
                const float e1 = (acc[rb][t][1] + b1 + x0 * w1) * sc;
                const float e2 = (acc[rb][t][2] + b0 + x1 * w0) * sc;
                const float e3 = (acc[rb][t][3] + b1 + x1 * w1) * sc;
                *(uint32_t*)&dst[(size_t)(row0 + r0l) * 64 + col] = pkh2(e0, e1);
                *(uint32_t*)&dst[(size_t)(row0 + r1l) * 64 + col] = pkh2(e2, e3);
            }
        }
    }

    // ---- phase 2: V^T. D[dim][l] = Wv^T x^T ----
    {
        __syncthreads();
        #pragma unroll
        for (int i = 0; i < 8; i++) {
            const int f = tid + i * 128;
            const int d = f >> 4, c4 = (f & 15) << 2;
            const float4 v = *(const float4*)&Wv[d * 64 + c4];
            char* p = sWc + swzh(d, c4 >> 3) + ((c4 & 7) << 1);
            *(uint32_t*)p       = pkh2(v.x, v.y);
            *(uint32_t*)(p + 4) = pkh2(v.z, v.w);
        }
        if (tid < 64) { sw64[tid] = Wv[64 * 64 + tid]; sbias[tid] = bv[tid]; }
        __syncthreads();

        // A frags: warp's 16 dims (trans-A: B-style addressing on [d][dim] tile)
        uint32_t aw[4][4];
        #pragma unroll
        for (int ks = 0; ks < 4; ks++)
            ldsm4t(sWb + swzh(16 * ks + rB, 2 * w + cB), aw[ks]);

        float acc[16][4];
        #pragma unroll
        for (int t = 0; t < 16; t++)
            #pragma unroll
            for (int e = 0; e < 4; e++) acc[t][e] = 0.f;

        #pragma unroll
        for (int tpl = 0; tpl < 8; tpl++)
            #pragma unroll
            for (int ks = 0; ks < 4; ks++) {
                uint32_t xb[4];
                ldsm4(sXb + swzh(16 * tpl + rB, 2 * ks + cB), xb);
                mma_f16(acc[2 * tpl],     aw[ks], xb[0], xb[1]);
                mma_f16(acc[2 * tpl + 1], aw[ks], xb[2], xb[3]);
            }

        const int bb = row0 >> 12, l0 = row0 & 4095;
        const int dim0 = 16 * w + i0, dim1 = dim0 + 8;
        const float bw0 = sbias[dim0] , bw1 = sbias[dim1];
        const float w0 = sw64[dim0], w1 = sw64[dim1];
        #pragma unroll
        for (int t = 0; t < 16; t++) {
            const int col = 8 * t + q2;
            const float xa = sx64[col], xb2 = sx64[col + 1];
            const float e0 = acc[t][0] + bw0 + w0 * xa;
            const float e1 = acc[t][1] + bw0 + w0 * xb2;
            const float e2 = acc[t][2] + bw1 + w1 * xa;
            const float e3 = acc[t][3] + bw1 + w1 * xb2;
            *(uint32_t*)&g_vT[(size_t)((bb << 6) + dim0) * SEQ + l0 + col] = pkh2(e0, e1);
            *(uint32_t*)&g_vT[(size_t)((bb << 6) + dim1) * SEQ + l0 + col] = pkh2(e2, e3);
        }
    }
}

// ============================ flash (fp16 mma, split-K, cp.async 2-stage) ============================
__global__ void __launch_bounds__(128, 2) flash_kernel()
{
    __shared__ __align__(16) __half sK[2][64 * 64];
    __shared__ __align__(16) __half sV[2][64 * 64];
    __shared__ __align__(16) __half sP[128 * 64];   // Q staging, then P; [0] aliased as queue slot

    const uint32_t sKb[2] = { smem_u32(sK[0]), smem_u32(sK[1]) };
    const uint32_t sVb[2] = { smem_u32(sV[0]), smem_u32(sV[1]) };
    const uint32_t sPb = smem_u32(sP);
    char* sPc = (char*)sP;

    const int tid  = threadIdx.x;
    const int lane = tid & 31;
    const int w    = tid >> 5;
    const int rowA = lane & 15;
    const int chA  = lane >> 4;
    const int rowB = (lane & 7) + ((lane >> 4) << 3);
    const int chB  = (lane >> 3) & 1;
    const int i0   = lane >> 2;
    const int q2   = (lane & 3) << 1;

    for (;;) {
        if (tid == 0)
            *(volatile unsigned*)sP = atomicAdd(&g_tile_ctr, 1u);
        __syncthreads();
        const unsigned unit = *(volatile unsigned*)sP;
        __syncthreads();
        if (unit >= NUNITS) break;

        // decode: heavy-first (qt descending), chunks of 16 K-iterations
        const int r = (int)(unit >> 3);
        const int b = (int)(unit & 7u);
        int qt, ch;
        if (r < 32)      { qt = 31 - (r >> 2); ch = r & 3; }
        else if (r < 56) { const int t = r - 32; const int q3 = t / 3; qt = 23 - q3; ch = t - 3 * q3; }
        else if (r < 72) { const int t = r - 56; qt = 15 - (t >> 1); ch = t & 1; }
        else             { qt = 7 - (r - 72); ch = 0; }
        const int nkt = 2 * qt + 2;
        const int kt0 = ch << 4;
        const int kt1 = (kt0 + 16 < nkt) ? kt0 + 16 : nkt;
        const int q0  = qt << 7;

        // ---- async fills: Q (into sP), then K/V stage 0 and 1 ----
        #pragma unroll
        for (int i = 0; i < 8; i++) {
            const int f = tid + i * 128;
            const int row = f >> 3, cc = f & 7;
            cpa16(sPb + swzh(row, cc), &g_q[(size_t)((b << 12) + q0 + row) * 64 + cc * 8]);
        }
        CP_COMMIT();
        {
            const int k0 = kt0 << 6;
            #pragma unroll
            for (int i = 0; i < 4; i++) {
                const int f = tid + i * 128;
                const int row = f >> 3, cc = f & 7;
                cpa16(sKb[0] + swzh(row, cc), &g_k[(size_t)((b << 12) + k0 + row) * 64 + cc * 8]);
                cpa16(sVb[0] + swzh(row, cc), &g_vT[(size_t)((b << 6) + row) * SEQ + k0 + cc * 8]);
            }
            CP_COMMIT();
        }
        const bool has2 = (kt0 + 1 < kt1);
        if (has2) {
            const int k0 = (kt0 + 1) << 6;
            #pragma unroll
            for (int i = 0; i < 4; i++) {
                const int f = tid + i * 128;
                const int row = f >> 3, cc = f & 7;
                cpa16(sKb[1] + swzh(row, cc), &g_k[(size_t)((b << 12) + k0 + row) * 64 + cc * 8]);
                cpa16(sVb[1] + swzh(row, cc), &g_vT[(size_t)((b << 6) + row) * SEQ + k0 + cc * 8]);
            }
            CP_COMMIT();
            CP_WAIT2();   // Q group retired
        } else {
            CP_WAIT1();
        }
        __syncthreads();

        // ---- Q fragments (A): 2 row-blocks x 4 k-steps ----
        uint32_t qa[2][4][4];
        #pragma unroll
        for (int rb = 0; rb < 2; rb++)
            #pragma unroll
            for (int ks = 0; ks < 4; ks++)
                ldsm4(sPb + swzh(32 * w + 16 * rb + rowA, 2 * ks + chA), qa[rb][ks]);
        __syncwarp();

        float o[2][8][4];
        #pragma unroll
        for (int rb = 0; rb < 2; rb++)
            #pragma unroll
            for (int t = 0; t < 8; t++)
                #pragma unroll
                for (int e = 0; e < 4; e++) o[rb][t][e] = 0.f;
        float rs[4] = {0.f, 0.f, 0.f, 0.f};

        for (int kt = kt0; kt < kt1; kt++) {
            const int cur = (kt - kt0) & 1;
            const int k0  = kt << 6;

            if (kt + 1 < kt1) { CP_WAIT1(); } else { CP_WAIT0(); }
            __syncthreads();   // buf[cur] filled & visible; prior-iter qa/P reads done

            // ---- MMA1: S = Q K^T ----
            float s[2][8][4];
            #pragma unroll
            for (int t = 0; t < 8; t++)
                #pragma unroll
                for (int e = 0; e < 4; e++) { s[0][t][e] = 0.f; s[1][t][e] = 0.f; }
            #pragma unroll
            for (int ks = 0; ks < 4; ks++)
                #pragma unroll
                for (int tp = 0; tp < 4; tp++) {
                    uint32_t kb[4];
                    ldsm4(sKb[cur] + swzh(16 * tp + rowB, 2 * ks + chB), kb);
                    mma_f16(s[0][2 * tp],     qa[0][ks], kb[0], kb[1]);
                    mma_f16(s[0][2 * tp + 1], qa[0][ks], kb[2], kb[3]);
                    mma_f16(s[1][2 * tp],     qa[1][ks], kb[0], kb[1]);
                    mma_f16(s[1][2 * tp + 1], qa[1][ks], kb[2], kb[3]);
                }

            // ---- softmax: exp (no max; scores small), row sums, P -> fp16 ----
            const bool diag = (kt >= 2 * qt);
            #pragma unroll
            for (int rb = 0; rb < 2; rb++) {
                const int r0 = q0 + 32 * w + 16 * rb + i0;
                const int r1 = r0 + 8;
                const int pr0 = 32 * w + 16 * rb + i0;
                float a0 = 0.f, a1 = 0.f;
                #pragma unroll
                for (int t = 0; t < 8; t++) {
                    const int key = k0 + 8 * t + q2;
                    float e0, e1, e2, e3;
                    if (diag) {
                        e0 = (key     <= r0) ? __expf(s[rb][t][0]) : 0.f;
                        e1 = (key + 1 <= r0) ? __expf(s[rb][t][1]) : 0.f;
                        e2 = (key     <= r1) ? __expf(s[rb][t][2]) : 0.f;
                        e3 = (key + 1 <= r1) ? __expf(s[rb][t][3]) : 0.f;
                    } else {
                        e0 = __expf(s[rb][t][0]);
                        e1 = __expf(s[rb][t][1]);
                        e2 = __expf(s[rb][t][2]);
                        e3 = __expf(s[rb][t][3]);
                    }
                    const uint32_t p01 = pkh2(e0, e1);
                    const uint32_t p23 = pkh2(e2, e3);
                    const __half2 h01 = *reinterpret_cast<const __half2*>(&p01);
                    const __half2 h23 = *reinterpret_cast<const __half2*>(&p23);
                    a0 += __half2float(__low2half(h01)) + __half2float(__high2half(h01));
                    a1 += __half2float(__low2half(h23)) + __half2float(__high2half(h23));
                    *(uint32_t*)(sPc + swzh(pr0,     t) + (q2 << 1)) = p01;
                    *(uint32_t*)(sPc + swzh(pr0 + 8, t) + (q2 << 1)) = p23;
                }
                rs[2 * rb] += a0; rs[2 * rb + 1] += a1;
            }
            __syncwarp();

            // ---- MMA2: O += P V ----
            #pragma unroll
            for (int ks = 0; ks < 4; ks++) {
                uint32_t pa[2][4];
                ldsm4(sPb + swzh(32 * w +      rowA, 2 * ks + chA), pa[0]);
                ldsm4(sPb + swzh(32 * w + 16 + rowA, 2 * ks + chA), pa[1]);
                #pragma unroll
                for (int tp = 0; tp < 4; tp++) {
                    uint32_t vb[4];
                    ldsm4(sVb[cur] + swzh(16 * tp + rowB, 2 * ks + chB), vb);
                    mma_f16(o[0][2 * tp],     pa[0], vb[0], vb[1]);
                    mma_f16(o[0][2 * tp + 1], pa[0], vb[2], vb[3]);
                    mma_f16(o[1][2 * tp],     pa[1], vb[0], vb[1]);
                    mma_f16(o[1][2 * tp + 1], pa[1], vb[2], vb[3]);
                }
            }

            __syncthreads();   // all reads of buf[cur] complete
            if (kt + 2 < kt1) {
                const int kn = (kt + 2) << 6;
                #pragma unroll
                for (int i = 0; i < 4; i++) {
                    const int f = tid + i * 128;
                    const int row = f >> 3, cc = f & 7;
                    cpa16(sKb[cur] + swzh(row, cc), &g_k[(size_t)((b << 12) + kn + row) * 64 + cc * 8]);
                    cpa16(sVb[cur] + swzh(row, cc), &g_vT[(size_t)((b << 6) + row) * SEQ + kn + cc * 8]);
                }
                CP_COMMIT();
            }
        }

        // ---- epilogue: reduce row sums, write un-normalized partials ----
        #pragma unroll
        for (int j = 0; j < 4; j++) {
            rs[j] += __shfl_xor_sync(0xffffffffu, rs[j], 1);
            rs[j] += __shfl_xor_sync(0xffffffffu, rs[j], 2);
        }
        const int slot = (((b << 5) + qt) << 2) + ch;
        float* po = &g_part[(size_t)slot << 13];
        #pragma unroll
        for (int rb = 0; rb < 2; rb++) {
            const int r0l = 32 * w + 16 * rb + i0;
            float* o0 = &po[r0l * 64];
            float* o1 = o0 + 8 * 64;
            #pragma unroll
            for (int t = 0; t < 8; t++) {
                *(float2*)&o0[8 * t + q2] = make_float2(o[rb][t][0], o[rb][t][1]);
                *(float2*)&o1[8 * t + q2] = make_float2(o[rb][t][2], o[rb][t][3]);
            }
            if ((lane & 3) == 0) {
                g_lpart[slot * 128 + r0l]     = rs[2 * rb];
                g_lpart[slot * 128 + r0l + 8] = rs[2 * rb + 1];
            }
        }
    }
}

// ============================ normalize / combine ============================
__global__ void __launch_bounds__(256) norm_kernel(float* __restrict__ out)
{
    const int tile = blockIdx.x;          // (b<<5)+qt
    const int b = tile >> 5, qt = tile & 31;
    const int nc = (qt + 8) >> 3;
    const int tid = threadIdx.x;
    const int row = tid >> 1;
    const int c0  = (tid & 1) << 5;
    const size_t base = (size_t)tile << 15;

    float acc[32];
    #pragma unroll
    for (int i = 0; i < 32; i++) acc[i] = 0.f;
    float l = 0.f;

    for (int c = 0; c < nc; c++) {
        const float* p = &g_part[base + ((size_t)c << 13) + row * 64 + c0];
        #pragma unroll
        for (int i = 0; i < 8; i++) {
            const float4 v = *(const float4*)&p[i * 4];
            acc[4 * i]     += v.x;
            acc[4 * i + 1] += v.y;
            acc[4 * i + 2] += v.z;
            acc[4 * i + 3] += v.w;
        }
        l += g_lpart[(tile * 4 + c) * 128 + row];
    }
    const float inv = 1.f / l;
    float* po = &out[(size_t)((b << 12) + (qt << 7) + row) * 64 + c0];
    #pragma unroll
    for (int i = 0; i < 8; i++)
        *(float4*)&po[i * 4] = make_float4(acc[4*i] * inv, acc[4*i+1] * inv,
                                           acc[4*i+2] * inv, acc[4*i+3] * inv);
}

// ============================ launch ============================
extern "C" void kernel_launch(void* const* d_in, const int* in_sizes, int n_in,
                              void* d_out, int out_size)
{
    const float* x  = (const float*)d_in[0];
    const float* Wq = (const float*)d_in[1];
    const float* bq = (const float*)d_in[2];
    const float* Wk = (const float*)d_in[3];
    const float* bk = (const float*)d_in[4];
    const float* Wv = (const float*)d_in[5];
    const float* bv = (const float*)d_in[6];
    float* out = (float*)d_out;

    proj_kernel<<<(BATCH * SEQ) / 128, 128>>>(x, Wq, bq, Wk, bk, Wv, bv);
    flash_kernel<<<296, 128>>>();          // persistent, 640 split-K units
    norm_kernel<<<256, 256>>>(out);
}